// round 6
// baseline (speedup 1.0000x reference)
#include <cuda_runtime.h>
#include <cuda_fp16.h>

// ---------------------------------------------------------------------------
// Fused BN -> sign(+-1) -> 3x3 conv -> bias -> ReLU, fp16 tensor-core
// implicit GEMM. Persistent CTAs, double-buffered pipeline, 3 CTAs/SM.
// Tile: 8 rows x 32 px x 32 co; warp = 1 row x 32 px x 32 co (WM=32).
// Weights pre-shuffled into per-thread mma B-fragments (LDS.64, no ldmatrix).
// ---------------------------------------------------------------------------

#define HW      65536
#define C_CH    32

#define QROWS   10           // 8 + 2 halo
#define QPX     34           // 32 + 2 halo
#define CIP     40           // ci stride (halfs) -> 80B px stride, ldsm-safe
#define QTILE   (QROWS * QPX * CIP)   // 13600 halfs
#define NWF     (9 * 2 * 4 * 32)      // 2304 uint2 weight frags

#define OFF_Q0  0
#define OFF_Q1  (QTILE * 2)
#define OFF_WF  (QTILE * 4)           // 54400
#define OFF_SC  (OFF_WF + NWF * 8)    // 72832
#define OFF_SB  (OFF_SC + 256)        // 73088
#define SMEM_BYTES (OFF_SB + 128)     // 73216

#define NT      256
#define NCTA    444                   // 3 per SM x 148
#define NTILES  4096                  // 16 b x 32 y x 8 x

__device__ __forceinline__ void ldsm_x4(unsigned &a0, unsigned &a1,
                                        unsigned &a2, unsigned &a3,
                                        unsigned addr) {
    asm volatile("ldmatrix.sync.aligned.m8n8.x4.shared.b16 {%0,%1,%2,%3}, [%4];"
                 : "=r"(a0), "=r"(a1), "=r"(a2), "=r"(a3) : "r"(addr));
}
__device__ __forceinline__ void mma16816(float &c0, float &c1, float &c2, float &c3,
                                         unsigned a0, unsigned a1, unsigned a2, unsigned a3,
                                         unsigned b0, unsigned b1) {
    asm volatile("mma.sync.aligned.m16n8k16.row.col.f32.f16.f16.f32 "
                 "{%0,%1,%2,%3},{%4,%5,%6,%7},{%8,%9},{%0,%1,%2,%3};"
                 : "+f"(c0), "+f"(c1), "+f"(c2), "+f"(c3)
                 : "r"(a0), "r"(a1), "r"(a2), "r"(a3), "r"(b0), "r"(b1));
}
__device__ __forceinline__ unsigned quant2(float f0, float f1, float4 s, bool ok) {
    float v0 = fmaf(f0, s.x, s.y);
    float v1 = fmaf(f1, s.z, s.w);
    unsigned lo = ok ? (v0 > 0.f ? 0x3C00u : 0xBC00u) : 0u;
    unsigned hi = ok ? (v1 > 0.f ? 0x3C00u : 0xBC00u) : 0u;
    return lo | (hi << 16);
}
__device__ __forceinline__ void sts32(unsigned addr, unsigned val) {
    asm volatile("st.shared.b32 [%0], %1;" :: "r"(addr), "r"(val));
}

// MMA over taps [T0,T1], k-stage S, on buffer qc.
template<int T0, int T1, int S>
__device__ __forceinline__ void mma_taps(unsigned qc, const uint2* __restrict__ wfragsm,
                                         int wr, int pxl0, int cih, int lane,
                                         float acc[2][4][4]) {
#pragma unroll
    for (int tap = T0; tap <= T1; ++tap) {
        const int dy = tap / 3, dx = tap % 3;
        uint2 wf[4];
#pragma unroll
        for (int nt = 0; nt < 4; ++nt)
            wf[nt] = wfragsm[((tap * 2 + S) * 4 + nt) * 32 + lane];
#pragma unroll
        for (int mt = 0; mt < 2; ++mt) {
            unsigned a0, a1, a2, a3;
            unsigned addr = qc +
                (((((wr + dy) * QPX) + mt * 16 + dx + pxl0) * CIP + cih + S * 16) << 1);
            ldsm_x4(a0, a1, a2, a3, addr);
#pragma unroll
            for (int nt = 0; nt < 4; ++nt)
                mma16816(acc[mt][nt][0], acc[mt][nt][1], acc[mt][nt][2], acc[mt][nt][3],
                         a0, a1, a2, a3, wf[nt].x, wf[nt].y);
        }
    }
}

__global__ __launch_bounds__(NT, 3)
void tbconv_wm32_kernel(const float* __restrict__ x,
                        const float* __restrict__ gamma,
                        const float* __restrict__ beta,
                        const float* __restrict__ mean,
                        const float* __restrict__ var,
                        const float* __restrict__ w,
                        const float* __restrict__ bias,
                        float* __restrict__ out)
{
    extern __shared__ char smraw[];
    uint2*  wfragsm = (uint2*)(smraw + OFF_WF);
    float4* sinvsh  = (float4*)(smraw + OFF_SC);
    float*  sbias   = (float*)(smraw + OFF_SB);

    const int tid  = threadIdx.x;
    const int lane = tid & 31;
    const int wid  = tid >> 5;      // warp = output row 0..7

    // ---- one-time setup ----
    if (tid < 16) {
        int c0 = 2 * tid;
        float i0 = gamma[c0]     * rsqrtf(var[c0]     + 1e-4f);
        float i1 = gamma[c0 + 1] * rsqrtf(var[c0 + 1] + 1e-4f);
        sinvsh[tid] = make_float4(i0, beta[c0]     - mean[c0]     * i0,
                                  i1, beta[c0 + 1] - mean[c0 + 1] * i1);
    }
    if (tid < 32) sbias[tid] = bias[tid];
    // weights pre-shuffled into mma B-fragment order:
    // wfrag[((tap*2+s)*4+nt)*32 + t] = {w2(ci,ci+1), w2(ci+8,ci+9)} for
    // co = nt*8 + t/4, ci = s*16 + (t%4)*2   (w is OIHW [co][ci][tap])
    for (int i = tid; i < NWF; i += NT) {
        int t = i & 31, nt = (i >> 5) & 3, s = (i >> 7) & 1, tap = i >> 8;
        int co = nt * 8 + (t >> 2);
        int ci = s * 16 + (t & 3) * 2;
        const float* wb = w + (co * 32 + ci) * 9 + tap;
        __half2 lo = __floats2half2_rn(wb[0],  wb[9]);    // ci, ci+1
        __half2 hi = __floats2half2_rn(wb[72], wb[81]);   // ci+8, ci+9
        uint2 v;
        v.x = *(unsigned*)&lo;
        v.y = *(unsigned*)&hi;
        wfragsm[i] = v;
    }

    const unsigned q0a = (unsigned)__cvta_generic_to_shared(smraw) + OFF_Q0;
    const unsigned q1a = q0a + QTILE * 2;

    const int wr   = wid;                        // output row within tile
    const int pxl0 = (lane & 7) + ((lane >> 3) & 1) * 8;
    const int cih  = (lane >> 4) * 8;
    const int m0   = lane >> 2;
    const int cb   = (lane & 3) * 2;

    // halo decode: set A = all 256 threads (rows 0..7), set B = tid<64 (rows 8..9)
    const int hside = tid & 1;
    const int hcp   = (tid >> 1) & 15;
    const int hr    = tid >> 5;          // 0..7
    const int h2r   = 8 + (tid >> 5);    // 8..9 (tid < 64)
    const int hpx   = hside ? 33 : 0;

    __syncthreads();   // sbias/sinvsh/wfrag visible

    float bias0[4], bias1[4];
#pragma unroll
    for (int nt = 0; nt < 4; ++nt) {
        bias0[nt] = sbias[nt * 8 + cb];
        bias1[nt] = sbias[nt * 8 + cb + 1];
    }

    float acc[2][4][4];
#pragma unroll
    for (int mt = 0; mt < 2; ++mt)
#pragma unroll
        for (int nt = 0; nt < 4; ++nt)
#pragma unroll
            for (int k = 0; k < 4; ++k) acc[mt][nt][k] = 0.0f;

    int tile = blockIdx.x;
    int b  = tile >> 8;
    int by = ((tile >> 3) & 31) << 3;
    int bx = (tile & 7) << 5;

    // ---- prologue: build first tile into q0 ----
    {
        const float* xb = x + (size_t)b * C_CH * HW;
#pragma unroll
        for (int k = 0; k < 20; ++k) {
            int item = wid + (k << 3);       // 0..159
            int r  = item >> 4, cp = item & 15;
            int gy = by + r - 1;
            bool ok = (unsigned)gy < 256u;
            float f0 = 0.f, f1 = 0.f;
            if (ok) {
                const float* p = xb + (size_t)(2 * cp) * HW + (gy << 8) + bx + lane;
                f0 = __ldg(p); f1 = __ldg(p + HW);
            }
            sts32(q0a + (((r * QPX + lane + 1) * CIP + 2 * cp) << 1),
                  quant2(f0, f1, sinvsh[cp], ok));
        }
        {   // halo A
            int gy = by + hr - 1, gx = bx + hpx - 1;
            bool ok = ((unsigned)gy < 256u) & ((unsigned)gx < 256u);
            float f0 = 0.f, f1 = 0.f;
            if (ok) {
                const float* p = xb + (size_t)(2 * hcp) * HW + (gy << 8) + gx;
                f0 = __ldg(p); f1 = __ldg(p + HW);
            }
            sts32(q0a + (((hr * QPX + hpx) * CIP + 2 * hcp) << 1),
                  quant2(f0, f1, sinvsh[hcp], ok));
        }
        if (tid < 64) {   // halo B
            int gy = by + h2r - 1, gx = bx + hpx - 1;
            bool ok = ((unsigned)gy < 256u) & ((unsigned)gx < 256u);
            float f0 = 0.f, f1 = 0.f;
            if (ok) {
                const float* p = xb + (size_t)(2 * hcp) * HW + (gy << 8) + gx;
                f0 = __ldg(p); f1 = __ldg(p + HW);
            }
            sts32(q0a + (((h2r * QPX + hpx) * CIP + 2 * hcp) << 1),
                  quant2(f0, f1, sinvsh[hcp], ok));
        }
    }
    __syncthreads();

    bool flip = false;

#define LOADS(J)                                                              \
    if (hasnext) {                                                            \
        _Pragma("unroll")                                                     \
        for (int k5 = 0; k5 < 5; ++k5) {                                      \
            int item = wid + (((J) * 5 + k5) << 3);                           \
            int r  = item >> 4, cp = item & 15;                               \
            int gy = nby + r - 1;                                             \
            float f0 = 0.f, f1 = 0.f;                                         \
            if ((unsigned)gy < 256u) {                                        \
                const float* p = xbn + (size_t)(2 * cp) * HW + (gy << 8) + nbx + lane; \
                f0 = __ldg(p); f1 = __ldg(p + HW);                            \
            }                                                                 \
            rf[k5][0] = f0; rf[k5][1] = f1;                                   \
        }                                                                     \
    }

#define STS_STAGE(J)                                                          \
    if (hasnext) {                                                            \
        _Pragma("unroll")                                                     \
        for (int k5 = 0; k5 < 5; ++k5) {                                      \
            int item = wid + (((J) * 5 + k5) << 3);                           \
            int r  = item >> 4, cp = item & 15;                               \
            bool ok = (unsigned)(nby + r - 1) < 256u;                         \
            sts32(qn + (((r * QPX + lane + 1) * CIP + 2 * cp) << 1),          \
                  quant2(rf[k5][0], rf[k5][1], sinvsh[cp], ok));              \
        }                                                                     \
    }

    while (true) {
        const unsigned qc = flip ? q1a : q0a;
        const unsigned qn = flip ? q0a : q1a;

        const int nxt = tile + NCTA;
        const bool hasnext = (nxt < NTILES);
        int nb = 0, nby = 0, nbx = 0;
        if (hasnext) {
            nb  = nxt >> 8;
            nby = ((nxt >> 3) & 31) << 3;
            nbx = (nxt & 7) << 5;
        }
        const float* xbn = x + (size_t)nb * C_CH * HW;

        float rf[5][2];
        float hA[2] = {0.f, 0.f}, hB[2] = {0.f, 0.f};

        LOADS(0)
        mma_taps<0, 4, 0>(qc, wfragsm, wr, pxl0, cih, lane, acc);
        STS_STAGE(0)
        LOADS(1)
        mma_taps<5, 8, 0>(qc, wfragsm, wr, pxl0, cih, lane, acc);
        STS_STAGE(1)
        LOADS(2)
        mma_taps<0, 4, 1>(qc, wfragsm, wr, pxl0, cih, lane, acc);
        STS_STAGE(2)
        LOADS(3)
        if (hasnext) {
            int gy = nby + hr - 1, gx = nbx + hpx - 1;
            if (((unsigned)gy < 256u) & ((unsigned)gx < 256u)) {
                const float* p = xbn + (size_t)(2 * hcp) * HW + (gy << 8) + gx;
                hA[0] = __ldg(p); hA[1] = __ldg(p + HW);
            }
            if (tid < 64) {
                int gy2 = nby + h2r - 1;
                if (((unsigned)gy2 < 256u) & ((unsigned)gx < 256u)) {
                    const float* p = xbn + (size_t)(2 * hcp) * HW + (gy2 << 8) + gx;
                    hB[0] = __ldg(p); hB[1] = __ldg(p + HW);
                }
            }
        }
        mma_taps<5, 8, 1>(qc, wfragsm, wr, pxl0, cih, lane, acc);
        STS_STAGE(3)
        if (hasnext) {
            bool okA = ((unsigned)(nby + hr - 1) < 256u) &
                       ((unsigned)(nbx + hpx - 1) < 256u);
            sts32(qn + (((hr * QPX + hpx) * CIP + 2 * hcp) << 1),
                  quant2(hA[0], hA[1], sinvsh[hcp], okA));
            if (tid < 64) {
                bool okB = ((unsigned)(nby + h2r - 1) < 256u) &
                           ((unsigned)(nbx + hpx - 1) < 256u);
                sts32(qn + (((h2r * QPX + hpx) * CIP + 2 * hcp) << 1),
                      quant2(hB[0], hB[1], sinvsh[hcp], okB));
            }
        }

        // ---- epilogue ----
        {
            float* ob = out + (size_t)b * C_CH * HW;
            const int oy = by + wr;
#pragma unroll
            for (int nt = 0; nt < 4; ++nt) {
                const int co = nt * 8 + cb;
                float* o0 = ob + (size_t)co * HW + (oy << 8);
                float* o1 = o0 + HW;
#pragma unroll
                for (int mt = 0; mt < 2; ++mt) {
                    const int px = bx + mt * 16 + m0;
                    o0[px]     = fmaxf(acc[mt][nt][0] + bias0[nt], 0.0f);
                    o1[px]     = fmaxf(acc[mt][nt][1] + bias1[nt], 0.0f);
                    o0[px + 8] = fmaxf(acc[mt][nt][2] + bias0[nt], 0.0f);
                    o1[px + 8] = fmaxf(acc[mt][nt][3] + bias1[nt], 0.0f);
                    acc[mt][nt][0] = 0.f; acc[mt][nt][1] = 0.f;
                    acc[mt][nt][2] = 0.f; acc[mt][nt][3] = 0.f;
                }
            }
        }

        __syncthreads();
        if (!hasnext) break;
        tile = nxt; b = nb; by = nby; bx = nbx;
        flip = !flip;
    }
#undef LOADS
#undef STS_STAGE
}

extern "C" void kernel_launch(void* const* d_in, const int* in_sizes, int n_in,
                              void* d_out, int out_size)
{
    const float* x     = (const float*)d_in[0];
    const float* gamma = (const float*)d_in[1];
    const float* beta  = (const float*)d_in[2];
    const float* mean  = (const float*)d_in[3];
    const float* var   = (const float*)d_in[4];
    const float* w     = (const float*)d_in[5];
    const float* bias  = (const float*)d_in[6];
    float* out = (float*)d_out;

    cudaFuncSetAttribute(tbconv_wm32_kernel,
                         cudaFuncAttributeMaxDynamicSharedMemorySize, SMEM_BYTES);

    tbconv_wm32_kernel<<<NCTA, NT, SMEM_BYTES>>>(x, gamma, beta, mean, var, w, bias, out);
}

// round 7
// speedup vs baseline: 1.0174x; 1.0174x over previous
#include <cuda_runtime.h>
#include <cuda_fp16.h>

// ---------------------------------------------------------------------------
// Fused BN -> sign(+-1) -> 3x3 conv -> bias -> ReLU, fp16 tensor-core
// implicit GEMM. Persistent CTAs, double-buffered pipeline, 3 CTAs/SM.
// Tile: 8 rows x 32 px x 32 co; warp = 1 row x 32 px x 32 co (WM=32).
// Weights pre-shuffled into per-thread mma B-fragments (LDS.64, no ldmatrix).
// ---------------------------------------------------------------------------

#define HW      65536
#define C_CH    32

#define QROWS   10           // 8 + 2 halo
#define QPX     34           // 32 + 2 halo
#define CIP     40           // ci stride (halfs) -> 80B px stride, ldsm-safe
#define QTILE   (QROWS * QPX * CIP)   // 13600 halfs
#define NWF     (9 * 2 * 4 * 32)      // 2304 uint2 weight frags

#define OFF_Q0  0
#define OFF_Q1  (QTILE * 2)
#define OFF_WF  (QTILE * 4)           // 54400
#define OFF_SC  (OFF_WF + NWF * 8)    // 72832
#define OFF_SB  (OFF_SC + 256)        // 73088
#define SMEM_BYTES (OFF_SB + 128)     // 73216

#define NT      256
#define NCTA    444                   // 3 per SM x 148
#define NTILES  4096                  // 16 b x 32 y x 8 x

__device__ __forceinline__ void ldsm_x4(unsigned &a0, unsigned &a1,
                                        unsigned &a2, unsigned &a3,
                                        unsigned addr) {
    asm volatile("ldmatrix.sync.aligned.m8n8.x4.shared.b16 {%0,%1,%2,%3}, [%4];"
                 : "=r"(a0), "=r"(a1), "=r"(a2), "=r"(a3) : "r"(addr));
}
__device__ __forceinline__ void mma16816(float &c0, float &c1, float &c2, float &c3,
                                         unsigned a0, unsigned a1, unsigned a2, unsigned a3,
                                         unsigned b0, unsigned b1) {
    asm volatile("mma.sync.aligned.m16n8k16.row.col.f32.f16.f16.f32 "
                 "{%0,%1,%2,%3},{%4,%5,%6,%7},{%8,%9},{%0,%1,%2,%3};"
                 : "+f"(c0), "+f"(c1), "+f"(c2), "+f"(c3)
                 : "r"(a0), "r"(a1), "r"(a2), "r"(a3), "r"(b0), "r"(b1));
}
__device__ __forceinline__ unsigned quant2(float f0, float f1, float4 s, bool ok) {
    float v0 = fmaf(f0, s.x, s.y);
    float v1 = fmaf(f1, s.z, s.w);
    unsigned lo = ok ? (v0 > 0.f ? 0x3C00u : 0xBC00u) : 0u;
    unsigned hi = ok ? (v1 > 0.f ? 0x3C00u : 0xBC00u) : 0u;
    return lo | (hi << 16);
}
__device__ __forceinline__ void sts32(unsigned addr, unsigned val) {
    asm volatile("st.shared.b32 [%0], %1;" :: "r"(addr), "r"(val));
}

// MMA over taps [T0,T1], k-stage S, on buffer qc.
template<int T0, int T1, int S>
__device__ __forceinline__ void mma_taps(unsigned qc, const uint2* __restrict__ wfragsm,
                                         int wr, int pxl0, int cih, int lane,
                                         float acc[2][4][4]) {
#pragma unroll
    for (int tap = T0; tap <= T1; ++tap) {
        const int dy = tap / 3, dx = tap % 3;
        uint2 wf[4];
#pragma unroll
        for (int nt = 0; nt < 4; ++nt)
            wf[nt] = wfragsm[((tap * 2 + S) * 4 + nt) * 32 + lane];
#pragma unroll
        for (int mt = 0; mt < 2; ++mt) {
            unsigned a0, a1, a2, a3;
            unsigned addr = qc +
                (((((wr + dy) * QPX) + mt * 16 + dx + pxl0) * CIP + cih + S * 16) << 1);
            ldsm_x4(a0, a1, a2, a3, addr);
#pragma unroll
            for (int nt = 0; nt < 4; ++nt)
                mma16816(acc[mt][nt][0], acc[mt][nt][1], acc[mt][nt][2], acc[mt][nt][3],
                         a0, a1, a2, a3, wf[nt].x, wf[nt].y);
        }
    }
}

__global__ __launch_bounds__(NT, 3)
void tbconv_wm32_kernel(const float* __restrict__ x,
                        const float* __restrict__ gamma,
                        const float* __restrict__ beta,
                        const float* __restrict__ mean,
                        const float* __restrict__ var,
                        const float* __restrict__ w,
                        const float* __restrict__ bias,
                        float* __restrict__ out)
{
    extern __shared__ char smraw[];
    uint2*  wfragsm = (uint2*)(smraw + OFF_WF);
    float4* sinvsh  = (float4*)(smraw + OFF_SC);
    float*  sbias   = (float*)(smraw + OFF_SB);

    const int tid  = threadIdx.x;
    const int lane = tid & 31;
    const int wid  = tid >> 5;      // warp = output row 0..7

    // ---- one-time setup ----
    if (tid < 16) {
        int c0 = 2 * tid;
        float i0 = gamma[c0]     * rsqrtf(var[c0]     + 1e-4f);
        float i1 = gamma[c0 + 1] * rsqrtf(var[c0 + 1] + 1e-4f);
        sinvsh[tid] = make_float4(i0, beta[c0]     - mean[c0]     * i0,
                                  i1, beta[c0 + 1] - mean[c0 + 1] * i1);
    }
    if (tid < 32) sbias[tid] = bias[tid];
    // weights pre-shuffled into mma B-fragment order:
    // wfrag[((tap*2+s)*4+nt)*32 + t] = {w2(ci,ci+1), w2(ci+8,ci+9)} for
    // co = nt*8 + t/4, ci = s*16 + (t%4)*2   (w is OIHW [co][ci][tap])
    for (int i = tid; i < NWF; i += NT) {
        int t = i & 31, nt = (i >> 5) & 3, s = (i >> 7) & 1, tap = i >> 8;
        int co = nt * 8 + (t >> 2);
        int ci = s * 16 + (t & 3) * 2;
        const float* wb = w + (co * 32 + ci) * 9 + tap;
        __half2 lo = __floats2half2_rn(wb[0],  wb[9]);    // ci, ci+1
        __half2 hi = __floats2half2_rn(wb[72], wb[81]);   // ci+8, ci+9
        uint2 v;
        v.x = *(unsigned*)&lo;
        v.y = *(unsigned*)&hi;
        wfragsm[i] = v;
    }

    const unsigned q0a = (unsigned)__cvta_generic_to_shared(smraw) + OFF_Q0;
    const unsigned q1a = q0a + QTILE * 2;

    const int wr   = wid;                        // output row within tile
    const int pxl0 = (lane & 7) + ((lane >> 3) & 1) * 8;
    const int cih  = (lane >> 4) * 8;
    const int m0   = lane >> 2;
    const int cb   = (lane & 3) * 2;

    // halo decode: set A = all 256 threads (rows 0..7), set B = tid<64 (rows 8..9)
    const int hside = tid & 1;
    const int hcp   = (tid >> 1) & 15;
    const int hr    = tid >> 5;          // 0..7
    const int h2r   = 8 + (tid >> 5);    // 8..9 (tid < 64)
    const int hpx   = hside ? 33 : 0;

    __syncthreads();   // sbias/sinvsh/wfrag visible

    float bias0[4], bias1[4];
#pragma unroll
    for (int nt = 0; nt < 4; ++nt) {
        bias0[nt] = sbias[nt * 8 + cb];
        bias1[nt] = sbias[nt * 8 + cb + 1];
    }

    float acc[2][4][4];
#pragma unroll
    for (int mt = 0; mt < 2; ++mt)
#pragma unroll
        for (int nt = 0; nt < 4; ++nt)
#pragma unroll
            for (int k = 0; k < 4; ++k) acc[mt][nt][k] = 0.0f;

    int tile = blockIdx.x;
    int b  = tile >> 8;
    int by = ((tile >> 3) & 31) << 3;
    int bx = (tile & 7) << 5;

    // ---- prologue: build first tile into q0 ----
    {
        const float* xb = x + (size_t)b * C_CH * HW;
#pragma unroll
        for (int k = 0; k < 20; ++k) {
            int item = wid + (k << 3);       // 0..159
            int r  = item >> 4, cp = item & 15;
            int gy = by + r - 1;
            bool ok = (unsigned)gy < 256u;
            float f0 = 0.f, f1 = 0.f;
            if (ok) {
                const float* p = xb + (size_t)(2 * cp) * HW + (gy << 8) + bx + lane;
                f0 = __ldg(p); f1 = __ldg(p + HW);
            }
            sts32(q0a + (((r * QPX + lane + 1) * CIP + 2 * cp) << 1),
                  quant2(f0, f1, sinvsh[cp], ok));
        }
        {   // halo A
            int gy = by + hr - 1, gx = bx + hpx - 1;
            bool ok = ((unsigned)gy < 256u) & ((unsigned)gx < 256u);
            float f0 = 0.f, f1 = 0.f;
            if (ok) {
                const float* p = xb + (size_t)(2 * hcp) * HW + (gy << 8) + gx;
                f0 = __ldg(p); f1 = __ldg(p + HW);
            }
            sts32(q0a + (((hr * QPX + hpx) * CIP + 2 * hcp) << 1),
                  quant2(f0, f1, sinvsh[hcp], ok));
        }
        if (tid < 64) {   // halo B
            int gy = by + h2r - 1, gx = bx + hpx - 1;
            bool ok = ((unsigned)gy < 256u) & ((unsigned)gx < 256u);
            float f0 = 0.f, f1 = 0.f;
            if (ok) {
                const float* p = xb + (size_t)(2 * hcp) * HW + (gy << 8) + gx;
                f0 = __ldg(p); f1 = __ldg(p + HW);
            }
            sts32(q0a + (((h2r * QPX + hpx) * CIP + 2 * hcp) << 1),
                  quant2(f0, f1, sinvsh[hcp], ok));
        }
    }
    __syncthreads();

    bool flip = false;

#define LOADS(J)                                                              \
    if (hasnext) {                                                            \
        _Pragma("unroll")                                                     \
        for (int k5 = 0; k5 < 5; ++k5) {                                      \
            int item = wid + (((J) * 5 + k5) << 3);                           \
            int r  = item >> 4, cp = item & 15;                               \
            int gy = nby + r - 1;                                             \
            float f0 = 0.f, f1 = 0.f;                                         \
            if ((unsigned)gy < 256u) {                                        \
                const float* p = xbn + (size_t)(2 * cp) * HW + (gy << 8) + nbx + lane; \
                f0 = __ldg(p); f1 = __ldg(p + HW);                            \
            }                                                                 \
            rf[k5][0] = f0; rf[k5][1] = f1;                                   \
        }                                                                     \
    }

#define STS_STAGE(J)                                                          \
    if (hasnext) {                                                            \
        _Pragma("unroll")                                                     \
        for (int k5 = 0; k5 < 5; ++k5) {                                      \
            int item = wid + (((J) * 5 + k5) << 3);                           \
            int r  = item >> 4, cp = item & 15;                               \
            bool ok = (unsigned)(nby + r - 1) < 256u;                         \
            sts32(qn + (((r * QPX + lane + 1) * CIP + 2 * cp) << 1),          \
                  quant2(rf[k5][0], rf[k5][1], sinvsh[cp], ok));              \
        }                                                                     \
    }

    while (true) {
        const unsigned qc = flip ? q1a : q0a;
        const unsigned qn = flip ? q0a : q1a;

        const int nxt = tile + NCTA;
        const bool hasnext = (nxt < NTILES);
        int nb = 0, nby = 0, nbx = 0;
        if (hasnext) {
            nb  = nxt >> 8;
            nby = ((nxt >> 3) & 31) << 3;
            nbx = (nxt & 7) << 5;
        }
        const float* xbn = x + (size_t)nb * C_CH * HW;

        float rf[5][2];
        float hA[2] = {0.f, 0.f}, hB[2] = {0.f, 0.f};

        LOADS(0)
        mma_taps<0, 4, 0>(qc, wfragsm, wr, pxl0, cih, lane, acc);
        STS_STAGE(0)
        LOADS(1)
        mma_taps<5, 8, 0>(qc, wfragsm, wr, pxl0, cih, lane, acc);
        STS_STAGE(1)
        LOADS(2)
        mma_taps<0, 4, 1>(qc, wfragsm, wr, pxl0, cih, lane, acc);
        STS_STAGE(2)
        LOADS(3)
        if (hasnext) {
            int gy = nby + hr - 1, gx = nbx + hpx - 1;
            if (((unsigned)gy < 256u) & ((unsigned)gx < 256u)) {
                const float* p = xbn + (size_t)(2 * hcp) * HW + (gy << 8) + gx;
                hA[0] = __ldg(p); hA[1] = __ldg(p + HW);
            }
            if (tid < 64) {
                int gy2 = nby + h2r - 1;
                if (((unsigned)gy2 < 256u) & ((unsigned)gx < 256u)) {
                    const float* p = xbn + (size_t)(2 * hcp) * HW + (gy2 << 8) + gx;
                    hB[0] = __ldg(p); hB[1] = __ldg(p + HW);
                }
            }
        }
        mma_taps<5, 8, 1>(qc, wfragsm, wr, pxl0, cih, lane, acc);
        STS_STAGE(3)
        if (hasnext) {
            bool okA = ((unsigned)(nby + hr - 1) < 256u) &
                       ((unsigned)(nbx + hpx - 1) < 256u);
            sts32(qn + (((hr * QPX + hpx) * CIP + 2 * hcp) << 1),
                  quant2(hA[0], hA[1], sinvsh[hcp], okA));
            if (tid < 64) {
                bool okB = ((unsigned)(nby + h2r - 1) < 256u) &
                           ((unsigned)(nbx + hpx - 1) < 256u);
                sts32(qn + (((h2r * QPX + hpx) * CIP + 2 * hcp) << 1),
                      quant2(hB[0], hB[1], sinvsh[hcp], okB));
            }
        }

        // ---- epilogue ----
        {
            float* ob = out + (size_t)b * C_CH * HW;
            const int oy = by + wr;
#pragma unroll
            for (int nt = 0; nt < 4; ++nt) {
                const int co = nt * 8 + cb;
                float* o0 = ob + (size_t)co * HW + (oy << 8);
                float* o1 = o0 + HW;
#pragma unroll
                for (int mt = 0; mt < 2; ++mt) {
                    const int px = bx + mt * 16 + m0;
                    o0[px]     = fmaxf(acc[mt][nt][0] + bias0[nt], 0.0f);
                    o1[px]     = fmaxf(acc[mt][nt][1] + bias1[nt], 0.0f);
                    o0[px + 8] = fmaxf(acc[mt][nt][2] + bias0[nt], 0.0f);
                    o1[px + 8] = fmaxf(acc[mt][nt][3] + bias1[nt], 0.0f);
                    acc[mt][nt][0] = 0.f; acc[mt][nt][1] = 0.f;
                    acc[mt][nt][2] = 0.f; acc[mt][nt][3] = 0.f;
                }
            }
        }

        __syncthreads();
        if (!hasnext) break;
        tile = nxt; b = nb; by = nby; bx = nbx;
        flip = !flip;
    }
#undef LOADS
#undef STS_STAGE
}

extern "C" void kernel_launch(void* const* d_in, const int* in_sizes, int n_in,
                              void* d_out, int out_size)
{
    const float* x     = (const float*)d_in[0];
    const float* gamma = (const float*)d_in[1];
    const float* beta  = (const float*)d_in[2];
    const float* mean  = (const float*)d_in[3];
    const float* var   = (const float*)d_in[4];
    const float* w     = (const float*)d_in[5];
    const float* bias  = (const float*)d_in[6];
    float* out = (float*)d_out;

    cudaFuncSetAttribute(tbconv_wm32_kernel,
                         cudaFuncAttributeMaxDynamicSharedMemorySize, SMEM_BYTES);

    tbconv_wm32_kernel<<<NCTA, NT, SMEM_BYTES>>>(x, gamma, beta, mean, var, w, bias, out);
}

// round 8
// speedup vs baseline: 1.0656x; 1.0475x over previous
#include <cuda_runtime.h>
#include <cuda_fp16.h>

// ---------------------------------------------------------------------------
// Fused BN -> sign(+-1) -> 3x3 conv -> bias -> ReLU, fp16 tensor-core
// implicit GEMM. Persistent CTAs, double-buffered pipeline, 3 CTAs/SM.
// Tile: 8 rows x 32 px x 32 co; warp = 1 row x 32 px x 32 co (WM=32).
// Build uses STS.128 (4 half2/thread) to cut bank-conflict wavefronts 4x.
// Weights pre-shuffled into per-thread mma B-fragments (LDS.128 nt-pairs).
// ---------------------------------------------------------------------------

#define HW      65536
#define C_CH    32

#define QROWS   10           // 8 + 2 halo
#define QPX     34           // 32 + 2 halo
#define CIP     40           // ci stride (halfs) -> 80B px stride, ldsm-safe
#define QTILE   (QROWS * QPX * CIP)   // 13600 halfs
#define NWF4    (9 * 2 * 2 * 32)      // 1152 uint4 weight frag pairs

#define OFF_Q0  0
#define OFF_Q1  (QTILE * 2)
#define OFF_WF  (QTILE * 4)            // 54400
#define OFF_SC  (OFF_WF + NWF4 * 16)   // 72832 : sinvsh float4[16]
#define OFF_SI  (OFF_SC + 256)         // 73088 : sinv4 float4[8]
#define OFF_SS  (OFF_SI + 128)         // 73216 : ssh4  float4[8]
#define OFF_SB  (OFF_SS + 128)         // 73344 : sbias float[32]
#define SMEM_BYTES (OFF_SB + 128)      // 73472

#define NT      256
#define NCTA    444                    // 3 per SM x 148
#define NTILES  4096                   // 16 b x 32 y x 8 x

__device__ __forceinline__ void ldsm_x4(unsigned &a0, unsigned &a1,
                                        unsigned &a2, unsigned &a3,
                                        unsigned addr) {
    asm volatile("ldmatrix.sync.aligned.m8n8.x4.shared.b16 {%0,%1,%2,%3}, [%4];"
                 : "=r"(a0), "=r"(a1), "=r"(a2), "=r"(a3) : "r"(addr));
}
__device__ __forceinline__ void mma16816(float &c0, float &c1, float &c2, float &c3,
                                         unsigned a0, unsigned a1, unsigned a2, unsigned a3,
                                         unsigned b0, unsigned b1) {
    asm volatile("mma.sync.aligned.m16n8k16.row.col.f32.f16.f16.f32 "
                 "{%0,%1,%2,%3},{%4,%5,%6,%7},{%8,%9},{%0,%1,%2,%3};"
                 : "+f"(c0), "+f"(c1), "+f"(c2), "+f"(c3)
                 : "r"(a0), "r"(a1), "r"(a2), "r"(a3), "r"(b0), "r"(b1));
}
__device__ __forceinline__ unsigned quant2(float f0, float f1, float4 s, bool ok) {
    float v0 = fmaf(f0, s.x, s.y);
    float v1 = fmaf(f1, s.z, s.w);
    unsigned lo = ok ? (v0 > 0.f ? 0x3C00u : 0xBC00u) : 0u;
    unsigned hi = ok ? (v1 > 0.f ? 0x3C00u : 0xBC00u) : 0u;
    return lo | (hi << 16);
}
// pack two signs from (f0,f1) with separate scale/shift
__device__ __forceinline__ unsigned pk2(float f0, float iv0, float sh0,
                                        float f1, float iv1, float sh1, bool ok) {
    unsigned lo = ok ? (fmaf(f0, iv0, sh0) > 0.f ? 0x3C00u : 0xBC00u) : 0u;
    unsigned hi = ok ? (fmaf(f1, iv1, sh1) > 0.f ? 0x3C00u : 0xBC00u) : 0u;
    return lo | (hi << 16);
}
__device__ __forceinline__ void sts32(unsigned addr, unsigned val) {
    asm volatile("st.shared.b32 [%0], %1;" :: "r"(addr), "r"(val));
}
__device__ __forceinline__ void sts128(unsigned addr, uint4 v) {
    asm volatile("st.shared.v4.b32 [%0], {%1,%2,%3,%4};"
                 :: "r"(addr), "r"(v.x), "r"(v.y), "r"(v.z), "r"(v.w));
}

// MMA over taps [T0,T1], k-stage S, on buffer qc. Weight frags via LDS.128.
template<int T0, int T1, int S>
__device__ __forceinline__ void mma_taps(unsigned qc, const uint4* __restrict__ wfragsm,
                                         int wr, int pxl0, int cih, int lane,
                                         float acc[2][4][4]) {
#pragma unroll
    for (int tap = T0; tap <= T1; ++tap) {
        const int dy = tap / 3, dx = tap % 3;
        uint4 wfa = wfragsm[(((tap * 2 + S) * 2) + 0) * 32 + lane];
        uint4 wfb = wfragsm[(((tap * 2 + S) * 2) + 1) * 32 + lane];
#pragma unroll
        for (int mt = 0; mt < 2; ++mt) {
            unsigned a0, a1, a2, a3;
            unsigned addr = qc +
                (((((wr + dy) * QPX) + mt * 16 + dx + pxl0) * CIP + cih + S * 16) << 1);
            ldsm_x4(a0, a1, a2, a3, addr);
            mma16816(acc[mt][0][0], acc[mt][0][1], acc[mt][0][2], acc[mt][0][3],
                     a0, a1, a2, a3, wfa.x, wfa.y);
            mma16816(acc[mt][1][0], acc[mt][1][1], acc[mt][1][2], acc[mt][1][3],
                     a0, a1, a2, a3, wfa.z, wfa.w);
            mma16816(acc[mt][2][0], acc[mt][2][1], acc[mt][2][2], acc[mt][2][3],
                     a0, a1, a2, a3, wfb.x, wfb.y);
            mma16816(acc[mt][3][0], acc[mt][3][1], acc[mt][3][2], acc[mt][3][3],
                     a0, a1, a2, a3, wfb.z, wfb.w);
        }
    }
}

__global__ __launch_bounds__(NT, 3)
void tbconv_sts128_kernel(const float* __restrict__ x,
                          const float* __restrict__ gamma,
                          const float* __restrict__ beta,
                          const float* __restrict__ mean,
                          const float* __restrict__ var,
                          const float* __restrict__ w,
                          const float* __restrict__ bias,
                          float* __restrict__ out)
{
    extern __shared__ char smraw[];
    uint4*  wfragsm = (uint4*)(smraw + OFF_WF);
    float4* sinvsh  = (float4*)(smraw + OFF_SC);   // [16] (i0,s0,i1,s1) per cp
    float4* sinv4   = (float4*)(smraw + OFF_SI);   // [8]  inv by ci quads
    float4* ssh4    = (float4*)(smraw + OFF_SS);   // [8]  shift by ci quads
    float*  sbias   = (float*)(smraw + OFF_SB);

    const int tid  = threadIdx.x;
    const int lane = tid & 31;
    const int wid  = tid >> 5;      // warp = output row 0..7

    // ---- one-time setup ----
    if (tid < 32) {
        int c = tid;
        float inv = gamma[c] * rsqrtf(var[c] + 1e-4f);
        float sh  = beta[c] - mean[c] * inv;
        ((float*)sinv4)[c] = inv;
        ((float*)ssh4)[c]  = sh;
        ((float*)sinvsh)[(c >> 1) * 4 + (c & 1) * 2]     = inv;
        ((float*)sinvsh)[(c >> 1) * 4 + (c & 1) * 2 + 1] = sh;
        sbias[c] = bias[c];
    }
    // weights pre-shuffled into mma B-fragment order, nt-paired uint4:
    // wfrag[((tap*2+s)*2+np)*32 + t] = frag(nt=2np) | frag(nt=2np+1)
    // frag(nt): {w2(ci,ci+1), w2(ci+8,ci+9)} for co = nt*8 + t/4,
    // ci = s*16 + (t%4)*2   (w is OIHW [co][ci][tap])
    for (int i = tid; i < NWF4; i += NT) {
        int t = i & 31, np = (i >> 5) & 1, s = (i >> 6) & 1, tap = i >> 7;
        int ci = s * 16 + (t & 3) * 2;
        const float* wb0 = w + ((np * 16 + (t >> 2)) * 32 + ci) * 9 + tap;
        const float* wb1 = wb0 + 8 * 32 * 9;
        __half2 lo0 = __floats2half2_rn(wb0[0],  wb0[9]);
        __half2 hi0 = __floats2half2_rn(wb0[72], wb0[81]);
        __half2 lo1 = __floats2half2_rn(wb1[0],  wb1[9]);
        __half2 hi1 = __floats2half2_rn(wb1[72], wb1[81]);
        uint4 v;
        v.x = *(unsigned*)&lo0; v.y = *(unsigned*)&hi0;
        v.z = *(unsigned*)&lo1; v.w = *(unsigned*)&hi1;
        wfragsm[i] = v;
    }

    const unsigned q0a = (unsigned)__cvta_generic_to_shared(smraw) + OFF_Q0;
    const unsigned q1a = q0a + QTILE * 2;

    const int wr   = wid;
    const int pxl0 = (lane & 7) + ((lane >> 3) & 1) * 8;
    const int cih  = (lane >> 4) * 8;
    const int m0   = lane >> 2;
    const int cb   = (lane & 3) * 2;

    // halo decode: set A = all 256 threads (rows 0..7), set B = tid<64 (rows 8..9)
    const int hside = tid & 1;
    const int hcp   = (tid >> 1) & 15;
    const int hr    = tid >> 5;          // 0..7
    const int h2r   = 8 + (tid >> 5);    // 8..9 (tid < 64)
    const int hpx   = hside ? 33 : 0;

    __syncthreads();   // setup visible

    float bias0[4], bias1[4];
#pragma unroll
    for (int nt = 0; nt < 4; ++nt) {
        bias0[nt] = sbias[nt * 8 + cb];
        bias1[nt] = sbias[nt * 8 + cb + 1];
    }

    float acc[2][4][4];
#pragma unroll
    for (int mt = 0; mt < 2; ++mt)
#pragma unroll
        for (int nt = 0; nt < 4; ++nt)
#pragma unroll
            for (int k = 0; k < 4; ++k) acc[mt][nt][k] = 0.0f;

    int tile = blockIdx.x;
    int b  = tile >> 8;
    int by = ((tile >> 3) & 31) << 3;
    int bx = (tile & 7) << 5;

    // ---- prologue: build first tile into q0 ----
    {
        const float* xb = x + (size_t)b * C_CH * HW;
#pragma unroll
        for (int k = 0; k < 5; ++k) {
            int item = wid + (k << 3);       // 0..39 : (r 0..9) x (cpb 0..3)
            int r = item >> 2, cpb = item & 3;
            int ci0 = cpb << 3;
            int gy = by + r - 1;
            bool ok = (unsigned)gy < 256u;
            float f[8];
#pragma unroll
            for (int j = 0; j < 8; ++j) f[j] = 0.f;
            if (ok) {
                const float* p = xb + (size_t)ci0 * HW + (gy << 8) + bx + lane;
#pragma unroll
                for (int j = 0; j < 8; ++j) f[j] = __ldg(p + (size_t)j * HW);
            }
            float4 i0 = sinv4[cpb * 2], i1 = sinv4[cpb * 2 + 1];
            float4 s0 = ssh4[cpb * 2],  s1 = ssh4[cpb * 2 + 1];
            uint4 v;
            v.x = pk2(f[0], i0.x, s0.x, f[1], i0.y, s0.y, ok);
            v.y = pk2(f[2], i0.z, s0.z, f[3], i0.w, s0.w, ok);
            v.z = pk2(f[4], i1.x, s1.x, f[5], i1.y, s1.y, ok);
            v.w = pk2(f[6], i1.z, s1.z, f[7], i1.w, s1.w, ok);
            sts128(q0a + (((r * QPX + lane + 1) * CIP + ci0) << 1), v);
        }
        {   // halo A
            int gy = by + hr - 1, gx = bx + hpx - 1;
            bool ok = ((unsigned)gy < 256u) & ((unsigned)gx < 256u);
            float f0 = 0.f, f1 = 0.f;
            if (ok) {
                const float* p = xb + (size_t)(2 * hcp) * HW + (gy << 8) + gx;
                f0 = __ldg(p); f1 = __ldg(p + HW);
            }
            sts32(q0a + (((hr * QPX + hpx) * CIP + 2 * hcp) << 1),
                  quant2(f0, f1, sinvsh[hcp], ok));
        }
        if (tid < 64) {   // halo B
            int gy = by + h2r - 1, gx = bx + hpx - 1;
            bool ok = ((unsigned)gy < 256u) & ((unsigned)gx < 256u);
            float f0 = 0.f, f1 = 0.f;
            if (ok) {
                const float* p = xb + (size_t)(2 * hcp) * HW + (gy << 8) + gx;
                f0 = __ldg(p); f1 = __ldg(p + HW);
            }
            sts32(q0a + (((h2r * QPX + hpx) * CIP + 2 * hcp) << 1),
                  quant2(f0, f1, sinvsh[hcp], ok));
        }
    }
    __syncthreads();

    bool flip = false;

#define LOADX(J, RF)                                                          \
    if (hasnext) {                                                            \
        int item = wid + ((J) << 3);                                          \
        int r = item >> 2, cpb = item & 3;                                    \
        int gy = nby + r - 1;                                                 \
        _Pragma("unroll")                                                     \
        for (int j = 0; j < 8; ++j) RF[j] = 0.f;                              \
        if ((unsigned)gy < 256u) {                                            \
            const float* p = xbn + (size_t)(cpb << 3) * HW + (gy << 8) + nbx + lane; \
            _Pragma("unroll")                                                 \
            for (int j = 0; j < 8; ++j) RF[j] = __ldg(p + (size_t)j * HW);    \
        }                                                                     \
    }

#define STSX(J, RF)                                                           \
    if (hasnext) {                                                            \
        int item = wid + ((J) << 3);                                          \
        int r = item >> 2, cpb = item & 3;                                    \
        int ci0 = cpb << 3;                                                   \
        bool ok = (unsigned)(nby + r - 1) < 256u;                             \
        float4 i0 = sinv4[cpb * 2], i1 = sinv4[cpb * 2 + 1];                  \
        float4 s0 = ssh4[cpb * 2],  s1 = ssh4[cpb * 2 + 1];                   \
        uint4 v;                                                              \
        v.x = pk2(RF[0], i0.x, s0.x, RF[1], i0.y, s0.y, ok);                  \
        v.y = pk2(RF[2], i0.z, s0.z, RF[3], i0.w, s0.w, ok);                  \
        v.z = pk2(RF[4], i1.x, s1.x, RF[5], i1.y, s1.y, ok);                  \
        v.w = pk2(RF[6], i1.z, s1.z, RF[7], i1.w, s1.w, ok);                  \
        sts128(qn + (((r * QPX + lane + 1) * CIP + ci0) << 1), v);            \
    }

    while (true) {
        const unsigned qc = flip ? q1a : q0a;
        const unsigned qn = flip ? q0a : q1a;

        const int nxt = tile + NCTA;
        const bool hasnext = (nxt < NTILES);
        int nb = 0, nby = 0, nbx = 0;
        if (hasnext) {
            nb  = nxt >> 8;
            nby = ((nxt >> 3) & 31) << 3;
            nbx = (nxt & 7) << 5;
        }
        const float* xbn = x + (size_t)nb * C_CH * HW;

        float rfA[8], rfB[8];
        float hA[2] = {0.f, 0.f}, hB[2] = {0.f, 0.f};

        LOADX(0, rfA)
        mma_taps<0, 2, 0>(qc, wfragsm, wr, pxl0, cih, lane, acc);
        STSX(0, rfA)
        LOADX(1, rfB)
        mma_taps<3, 5, 0>(qc, wfragsm, wr, pxl0, cih, lane, acc);
        STSX(1, rfB)
        LOADX(2, rfA)
        mma_taps<6, 8, 0>(qc, wfragsm, wr, pxl0, cih, lane, acc);
        STSX(2, rfA)
        LOADX(3, rfB)
        mma_taps<0, 2, 1>(qc, wfragsm, wr, pxl0, cih, lane, acc);
        STSX(3, rfB)
        LOADX(4, rfA)
        mma_taps<3, 5, 1>(qc, wfragsm, wr, pxl0, cih, lane, acc);
        STSX(4, rfA)
        if (hasnext) {      // halo loads
            int gy = nby + hr - 1, gx = nbx + hpx - 1;
            if (((unsigned)gy < 256u) & ((unsigned)gx < 256u)) {
                const float* p = xbn + (size_t)(2 * hcp) * HW + (gy << 8) + gx;
                hA[0] = __ldg(p); hA[1] = __ldg(p + HW);
            }
            if (tid < 64) {
                int gy2 = nby + h2r - 1;
                if (((unsigned)gy2 < 256u) & ((unsigned)gx < 256u)) {
                    const float* p = xbn + (size_t)(2 * hcp) * HW + (gy2 << 8) + gx;
                    hB[0] = __ldg(p); hB[1] = __ldg(p + HW);
                }
            }
        }
        mma_taps<6, 8, 1>(qc, wfragsm, wr, pxl0, cih, lane, acc);
        if (hasnext) {      // halo stores
            bool okA = ((unsigned)(nby + hr - 1) < 256u) &
                       ((unsigned)(nbx + hpx - 1) < 256u);
            sts32(qn + (((hr * QPX + hpx) * CIP + 2 * hcp) << 1),
                  quant2(hA[0], hA[1], sinvsh[hcp], okA));
            if (tid < 64) {
                bool okB = ((unsigned)(nby + h2r - 1) < 256u) &
                           ((unsigned)(nbx + hpx - 1) < 256u);
                sts32(qn + (((h2r * QPX + hpx) * CIP + 2 * hcp) << 1),
                      quant2(hB[0], hB[1], sinvsh[hcp], okB));
            }
        }

        // ---- epilogue ----
        {
            float* ob = out + (size_t)b * C_CH * HW;
            const int oy = by + wr;
#pragma unroll
            for (int nt = 0; nt < 4; ++nt) {
                const int co = nt * 8 + cb;
                float* o0 = ob + (size_t)co * HW + (oy << 8);
                float* o1 = o0 + HW;
#pragma unroll
                for (int mt = 0; mt < 2; ++mt) {
                    const int px = bx + mt * 16 + m0;
                    o0[px]     = fmaxf(acc[mt][nt][0] + bias0[nt], 0.0f);
                    o1[px]     = fmaxf(acc[mt][nt][1] + bias1[nt], 0.0f);
                    o0[px + 8] = fmaxf(acc[mt][nt][2] + bias0[nt], 0.0f);
                    o1[px + 8] = fmaxf(acc[mt][nt][3] + bias1[nt], 0.0f);
                    acc[mt][nt][0] = 0.f; acc[mt][nt][1] = 0.f;
                    acc[mt][nt][2] = 0.f; acc[mt][nt][3] = 0.f;
                }
            }
        }

        __syncthreads();
        if (!hasnext) break;
        tile = nxt; b = nb; by = nby; bx = nbx;
        flip = !flip;
    }
#undef LOADX
#undef STSX
}

extern "C" void kernel_launch(void* const* d_in, const int* in_sizes, int n_in,
                              void* d_out, int out_size)
{
    const float* x     = (const float*)d_in[0];
    const float* gamma = (const float*)d_in[1];
    const float* beta  = (const float*)d_in[2];
    const float* mean  = (const float*)d_in[3];
    const float* var   = (const float*)d_in[4];
    const float* w     = (const float*)d_in[5];
    const float* bias  = (const float*)d_in[6];
    float* out = (float*)d_out;

    cudaFuncSetAttribute(tbconv_sts128_kernel,
                         cudaFuncAttributeMaxDynamicSharedMemorySize, SMEM_BYTES);

    tbconv_sts128_kernel<<<NCTA, NT, SMEM_BYTES>>>(x, gamma, beta, mean, var, w, bias, out);
}

// round 10
// speedup vs baseline: 1.2841x; 1.2050x over previous
#include <cuda_runtime.h>
#include <cuda_fp16.h>

// ---------------------------------------------------------------------------
// Fused BN -> sign(+-1) -> 3x3 conv -> bias -> ReLU, fp16 tensor-core
// implicit GEMM. Persistent CTAs, double-buffered tiles, WARP-SPECIALIZED:
// warps 0-3 do MMA (2 rows x 32 px x 32 co each), warps 4-7 build the next
// tile concurrently. 2 CTAs/SM. Tile: 8 rows x 32 px x 32 co.
// ---------------------------------------------------------------------------

#define HW      65536
#define C_CH    32

#define QROWS   10           // 8 + 2 halo
#define QPX     34           // 32 + 2 halo
#define CIP     40           // ci stride (halfs) -> 80B px stride, ldsm-safe
#define QTILE   (QROWS * QPX * CIP)   // 13600 halfs
#define NWF4    (9 * 2 * 2 * 32)      // 1152 uint4 weight frag pairs

#define OFF_Q0  0
#define OFF_Q1  (QTILE * 2)
#define OFF_WF  (QTILE * 4)            // 54400
#define OFF_SI  (OFF_WF + NWF4 * 16)   // 72832 : sinvf float[32]
#define OFF_SS  (OFF_SI + 128)         // sshf  float[32]
#define OFF_SB  (OFF_SS + 128)         // sbias float[32]
#define SMEM_BYTES (OFF_SB + 128)

#define NT      256
#define NCTA    296                    // 2 per SM x 148
#define NTILES  4096                   // 16 b x 32 y x 8 x

__device__ __forceinline__ void ldsm_x4(unsigned &a0, unsigned &a1,
                                        unsigned &a2, unsigned &a3,
                                        unsigned addr) {
    asm volatile("ldmatrix.sync.aligned.m8n8.x4.shared.b16 {%0,%1,%2,%3}, [%4];"
                 : "=r"(a0), "=r"(a1), "=r"(a2), "=r"(a3) : "r"(addr));
}
__device__ __forceinline__ void mma16816(float &c0, float &c1, float &c2, float &c3,
                                         unsigned a0, unsigned a1, unsigned a2, unsigned a3,
                                         unsigned b0, unsigned b1) {
    asm volatile("mma.sync.aligned.m16n8k16.row.col.f32.f16.f16.f32 "
                 "{%0,%1,%2,%3},{%4,%5,%6,%7},{%8,%9},{%0,%1,%2,%3};"
                 : "+f"(c0), "+f"(c1), "+f"(c2), "+f"(c3)
                 : "r"(a0), "r"(a1), "r"(a2), "r"(a3), "r"(b0), "r"(b1));
}
__device__ __forceinline__ unsigned pk2(float f0, float iv0, float sh0,
                                        float f1, float iv1, float sh1, bool ok) {
    unsigned lo = ok ? (fmaf(f0, iv0, sh0) > 0.f ? 0x3C00u : 0xBC00u) : 0u;
    unsigned hi = ok ? (fmaf(f1, iv1, sh1) > 0.f ? 0x3C00u : 0xBC00u) : 0u;
    return lo | (hi << 16);
}
__device__ __forceinline__ void sts128(unsigned addr, uint4 v) {
    asm volatile("st.shared.v4.b32 [%0], {%1,%2,%3,%4};"
                 :: "r"(addr), "r"(v.x), "r"(v.y), "r"(v.z), "r"(v.w));
}

// load one body row-group: 8 ci (group g) x 32 px for stored row r
__device__ __forceinline__ void ldrow(const float* __restrict__ xb,
                                      int by, int bx, int r, int g, int lane,
                                      float* F) {
    int gy = by + r - 1;
    bool ok = (unsigned)gy < 256u;
#pragma unroll
    for (int j = 0; j < 8; ++j) F[j] = 0.f;
    if (ok) {
        const float* p = xb + (size_t)(g * 8) * HW + (gy << 8) + bx + lane;
#pragma unroll
        for (int j = 0; j < 8; ++j) F[j] = __ldg(p + (size_t)j * HW);
    }
}
__device__ __forceinline__ void strow(unsigned qn, int by, int r, int g, int lane,
                                      const float* ivr, const float* shr,
                                      const float* F) {
    bool ok = (unsigned)(by + r - 1) < 256u;
    uint4 v;
    v.x = pk2(F[0], ivr[0], shr[0], F[1], ivr[1], shr[1], ok);
    v.y = pk2(F[2], ivr[2], shr[2], F[3], ivr[3], shr[3], ok);
    v.z = pk2(F[4], ivr[4], shr[4], F[5], ivr[5], shr[5], ok);
    v.w = pk2(F[6], ivr[6], shr[6], F[7], ivr[7], shr[7], ok);
    sts128(qn + (((r * QPX + lane + 1) * CIP + g * 8) << 1), v);
}
// halo item ht in [0,80): (r 0..9, side 0..1, oct 0..3), px 0 or 33
__device__ __forceinline__ void halo_item(unsigned qn, const float* __restrict__ xb,
                                          int by, int bx, int ht,
                                          const float* sinvf, const float* sshf) {
    if (ht >= 80) return;
    int r = ht >> 3, side = (ht >> 2) & 1, oct = ht & 3;
    int px = side ? 33 : 0;
    int gy = by + r - 1, gx = bx + px - 1;
    bool ok = ((unsigned)gy < 256u) & ((unsigned)gx < 256u);
    float f[8];
#pragma unroll
    for (int j = 0; j < 8; ++j) f[j] = 0.f;
    if (ok) {
        const float* p = xb + (size_t)(oct * 8) * HW + (gy << 8) + gx;
#pragma unroll
        for (int j = 0; j < 8; ++j) f[j] = __ldg(p + (size_t)j * HW);
    }
    const float* iv = sinvf + oct * 8;
    const float* sh = sshf + oct * 8;
    uint4 v;
    v.x = pk2(f[0], iv[0], sh[0], f[1], iv[1], sh[1], ok);
    v.y = pk2(f[2], iv[2], sh[2], f[3], iv[3], sh[3], ok);
    v.z = pk2(f[4], iv[4], sh[4], f[5], iv[5], sh[5], ok);
    v.w = pk2(f[6], iv[6], sh[6], f[7], iv[7], sh[7], ok);
    sts128(qn + (((r * QPX + px) * CIP + oct * 8) << 1), v);
}

__global__ __launch_bounds__(NT, 2)
void tbconv_wspec_kernel(const float* __restrict__ x,
                         const float* __restrict__ gamma,
                         const float* __restrict__ beta,
                         const float* __restrict__ mean,
                         const float* __restrict__ var,
                         const float* __restrict__ w,
                         const float* __restrict__ bias,
                         float* __restrict__ out)
{
    extern __shared__ char smraw[];
    uint4* wfragsm = (uint4*)(smraw + OFF_WF);
    float* sinvf   = (float*)(smraw + OFF_SI);
    float* sshf    = (float*)(smraw + OFF_SS);
    float* sbias   = (float*)(smraw + OFF_SB);

    const int tid  = threadIdx.x;
    const int lane = tid & 31;
    const int wid  = tid >> 5;

    // ---- one-time setup ----
    if (tid < 32) {
        float inv = gamma[tid] * rsqrtf(var[tid] + 1e-4f);
        sinvf[tid] = inv;
        sshf[tid]  = beta[tid] - mean[tid] * inv;
        sbias[tid] = bias[tid];
    }
    // weights pre-shuffled into mma B-fragment order, nt-paired uint4 (as R8):
    for (int i = tid; i < NWF4; i += NT) {
        int t = i & 31, np = (i >> 5) & 1, s = (i >> 6) & 1, tap = i >> 7;
        int ci = s * 16 + (t & 3) * 2;
        const float* wb0 = w + ((np * 16 + (t >> 2)) * 32 + ci) * 9 + tap;
        const float* wb1 = wb0 + 8 * 32 * 9;
        __half2 lo0 = __floats2half2_rn(wb0[0],  wb0[9]);
        __half2 hi0 = __floats2half2_rn(wb0[72], wb0[81]);
        __half2 lo1 = __floats2half2_rn(wb1[0],  wb1[9]);
        __half2 hi1 = __floats2half2_rn(wb1[72], wb1[81]);
        uint4 v;
        v.x = *(unsigned*)&lo0; v.y = *(unsigned*)&hi0;
        v.z = *(unsigned*)&lo1; v.w = *(unsigned*)&hi1;
        wfragsm[i] = v;
    }

    const unsigned q0a = (unsigned)__cvta_generic_to_shared(smraw) + OFF_Q0;
    const unsigned q1a = q0a + QTILE * 2;

    const int pxl0 = (lane & 7) + ((lane >> 3) & 1) * 8;
    const int cih  = (lane >> 4) * 8;
    const int m0   = lane >> 2;
    const int cb   = (lane & 3) * 2;

    int tile = blockIdx.x;
    int b  = tile >> 8;
    int by = ((tile >> 3) & 31) << 3;
    int bx = (tile & 7) << 5;

    __syncthreads();   // setup visible

    // BN constants in registers (used by builders; cheap for all)
    float ivr[8], shr[8];
    {
        int g8 = (wid & 3) * 8;
#pragma unroll
        for (int j = 0; j < 8; ++j) { ivr[j] = sinvf[g8 + j]; shr[j] = sshf[g8 + j]; }
    }

    // ---- prologue: ALL 8 warps build tile 0 into q0 ----
    {
        const float* xb = x + (size_t)b * C_CH * HW;
        int g = wid & 3;
        int rbase = (wid >> 2) * 5;     // warps 0-3: rows 0-4; warps 4-7: rows 5-9
        float F[8];
#pragma unroll
        for (int k = 0; k < 5; ++k) {
            ldrow(xb, by, bx, rbase + k, g, lane, F);
            strow(q0a, by, rbase + k, g, lane, ivr, shr, F);
        }
        halo_item(q0a, xb, by, bx, tid, sinvf, sshf);
    }
    __syncthreads();

    float bias0[4], bias1[4];
#pragma unroll
    for (int nt = 0; nt < 4; ++nt) {
        bias0[nt] = sbias[nt * 8 + cb];
        bias1[nt] = sbias[nt * 8 + cb + 1];
    }

    bool flip = false;

    while (true) {
        const unsigned qc = flip ? q1a : q0a;
        const unsigned qn = flip ? q0a : q1a;

        const int nxt = tile + NCTA;
        const bool hasnext = (nxt < NTILES);
        int nb = 0, nby = 0, nbx = 0;
        if (hasnext) {
            nb  = nxt >> 8;
            nby = ((nxt >> 3) & 31) << 3;
            nbx = (nxt & 7) << 5;
        }

        if (wid < 4) {
            // ================= MMA role: 2 rows x 32 px x 32 co =================
            const int r0 = wid * 2;
            float acc[2][2][4][4];
#pragma unroll
            for (int rr = 0; rr < 2; ++rr)
#pragma unroll
                for (int mt = 0; mt < 2; ++mt)
#pragma unroll
                    for (int nt = 0; nt < 4; ++nt)
#pragma unroll
                        for (int k = 0; k < 4; ++k) acc[rr][mt][nt][k] = 0.f;

#pragma unroll
            for (int tap = 0; tap < 9; ++tap) {
                const int dy = tap / 3, dx = tap % 3;
#pragma unroll
                for (int S = 0; S < 2; ++S) {
                    uint4 wfa = wfragsm[(((tap * 2 + S) * 2) + 0) * 32 + lane];
                    uint4 wfb = wfragsm[(((tap * 2 + S) * 2) + 1) * 32 + lane];
#pragma unroll
                    for (int rr = 0; rr < 2; ++rr) {
#pragma unroll
                        for (int mt = 0; mt < 2; ++mt) {
                            unsigned a0, a1, a2, a3;
                            unsigned addr = qc +
                                ((((r0 + rr + dy) * QPX + mt * 16 + dx + pxl0) * CIP
                                  + cih + S * 16) << 1);
                            ldsm_x4(a0, a1, a2, a3, addr);
                            mma16816(acc[rr][mt][0][0], acc[rr][mt][0][1],
                                     acc[rr][mt][0][2], acc[rr][mt][0][3],
                                     a0, a1, a2, a3, wfa.x, wfa.y);
                            mma16816(acc[rr][mt][1][0], acc[rr][mt][1][1],
                                     acc[rr][mt][1][2], acc[rr][mt][1][3],
                                     a0, a1, a2, a3, wfa.z, wfa.w);
                            mma16816(acc[rr][mt][2][0], acc[rr][mt][2][1],
                                     acc[rr][mt][2][2], acc[rr][mt][2][3],
                                     a0, a1, a2, a3, wfb.x, wfb.y);
                            mma16816(acc[rr][mt][3][0], acc[rr][mt][3][1],
                                     acc[rr][mt][3][2], acc[rr][mt][3][3],
                                     a0, a1, a2, a3, wfb.z, wfb.w);
                        }
                    }
                }
            }
            // epilogue: bias + ReLU + store
            float* ob = out + (size_t)b * C_CH * HW;
#pragma unroll
            for (int rr = 0; rr < 2; ++rr) {
                const int oy = by + r0 + rr;
#pragma unroll
                for (int nt = 0; nt < 4; ++nt) {
                    const int co = nt * 8 + cb;
                    float* o0 = ob + (size_t)co * HW + (oy << 8);
                    float* o1 = o0 + HW;
#pragma unroll
                    for (int mt = 0; mt < 2; ++mt) {
                        const int px = bx + mt * 16 + m0;
                        o0[px]     = fmaxf(acc[rr][mt][nt][0] + bias0[nt], 0.0f);
                        o1[px]     = fmaxf(acc[rr][mt][nt][1] + bias1[nt], 0.0f);
                        o0[px + 8] = fmaxf(acc[rr][mt][nt][2] + bias0[nt], 0.0f);
                        o1[px + 8] = fmaxf(acc[rr][mt][nt][3] + bias1[nt], 0.0f);
                    }
                }
            }
        } else if (hasnext) {
            // ================= build role: tile i+1 into qn =================
            const float* xbn = x + (size_t)nb * C_CH * HW;
            const int g = wid & 3;           // ci group = builder index
            float FA[8], FB[8];
            ldrow(xbn, nby, nbx, 0, g, lane, FA);
#pragma unroll
            for (int r = 0; r < 10; r += 2) {
                ldrow(xbn, nby, nbx, r + 1, g, lane, FB);
                strow(qn, nby, r, g, lane, ivr, shr, FA);
                if (r + 2 < 10) ldrow(xbn, nby, nbx, r + 2, g, lane, FA);
                strow(qn, nby, r + 1, g, lane, ivr, shr, FB);
            }
            halo_item(qn, xbn, nby, nbx, g * 32 + lane, sinvf, sshf);
        }

        __syncthreads();
        if (!hasnext) break;
        tile = nxt; b = nb; by = nby; bx = nbx;
        flip = !flip;
    }
}

extern "C" void kernel_launch(void* const* d_in, const int* in_sizes, int n_in,
                              void* d_out, int out_size)
{
    const float* x     = (const float*)d_in[0];
    const float* gamma = (const float*)d_in[1];
    const float* beta  = (const float*)d_in[2];
    const float* mean  = (const float*)d_in[3];
    const float* var   = (const float*)d_in[4];
    const float* w     = (const float*)d_in[5];
    const float* bias  = (const float*)d_in[6];
    float* out = (float*)d_out;

    cudaFuncSetAttribute(tbconv_wspec_kernel,
                         cudaFuncAttributeMaxDynamicSharedMemorySize, SMEM_BYTES);

    tbconv_wspec_kernel<<<NCTA, NT, SMEM_BYTES>>>(x, gamma, beta, mean, var, w, bias, out);
}